// round 12
// baseline (speedup 1.0000x reference)
#include <cuda_runtime.h>
#include <cuda_fp16.h>
#include <math.h>
#include <stdint.h>

// Problem dims (fixed by the dataset)
#define BB   16
#define CC   392
#define HWP  4096          // 64*64 pixels
#define NH   8
#define HD   49            // head dim
#define HID  1568          // 4*C
#define C3   1176          // 3*C

#define MT_QKV  10
#define MT_C    4
#define MT_HID  13
// 32-wide k-groups in the permuted weight layout, padded to even count (KT=64)
#define KC32_C    14       // ceil(392/64)*2
#define KC32_HID  50       // ceil(1568/64)*2

// ---------------- scratch (static device, no allocs) ----------------
__device__ __half g_xh  [(size_t)BB * CC  * HWP];   // fp16 copy of x
__device__ __half g_qkv [(size_t)BB * C3  * HWP];
__device__ __half g_attn[(size_t)BB * CC  * HWP];
__device__ __half g_x2h [(size_t)BB * CC  * HWP];   // fp16 residual trunk
__device__ __half g_mlp [(size_t)BB * HID * HWP];
// fragment-permuted fp16 weights: [mtile][k32grp][kstep2][mb8][lane32] x uint4
__device__ uint4 g_w1p [(size_t)MT_QKV * KC32_C   * 512];
__device__ uint4 g_wpp [(size_t)MT_C   * KC32_C   * 512];
__device__ uint4 g_w2p [(size_t)MT_HID * KC32_C   * 512];
__device__ uint4 g_w3p [(size_t)MT_C   * KC32_HID * 512];
__device__ float g_s1  [C3],  g_cb1[C3];
__device__ float g_s2  [HID], g_cb2[HID];
__device__ float g_mu1 [(size_t)BB * HWP], g_iv1[(size_t)BB * HWP];

// ================= helpers =================
__device__ __forceinline__ uint32_t smem_u32(const void* p) {
    uint32_t a;
    asm("{ .reg .u64 t; cvta.to.shared.u64 t, %1; cvt.u32.u64 %0, t; }"
        : "=r"(a) : "l"(p));
    return a;
}
__device__ __forceinline__ void cp16(uint32_t saddr, const void* g, bool valid) {
    unsigned long long ga;
    asm("cvta.to.global.u64 %0, %1;" : "=l"(ga) : "l"(g));
    int sz = valid ? 16 : 0;
    asm volatile("cp.async.cg.shared.global [%0], [%1], 16, %2;"
                 :: "r"(saddr), "l"(ga), "r"(sz));
}
#define CP_COMMIT() asm volatile("cp.async.commit_group;" ::: "memory")
#define CP_WAIT1()  asm volatile("cp.async.wait_group 1;" ::: "memory")
#define CP_WAIT0()  asm volatile("cp.async.wait_group 0;" ::: "memory")

__device__ __forceinline__ uint32_t pack2(float a, float b) {
    __half2 h = __floats2half2_rn(a, b);
    return *reinterpret_cast<uint32_t*>(&h);
}
__device__ __forceinline__ void mma_f16(float* d, const uint32_t* a, const uint32_t* b) {
    asm volatile(
        "mma.sync.aligned.m16n8k16.row.col.f32.f16.f16.f32 "
        "{%0,%1,%2,%3}, {%4,%5,%6,%7}, {%8,%9}, {%0,%1,%2,%3};"
        : "+f"(d[0]), "+f"(d[1]), "+f"(d[2]), "+f"(d[3])
        : "r"(a[0]), "r"(a[1]), "r"(a[2]), "r"(a[3]), "r"(b[0]), "r"(b[1]));
}
__device__ __forceinline__ void ldmx4t(uint32_t& r0, uint32_t& r1,
                                       uint32_t& r2, uint32_t& r3, uint32_t addr) {
    asm volatile("ldmatrix.sync.aligned.m8n8.x4.trans.shared.b16 {%0,%1,%2,%3}, [%4];"
        : "=r"(r0), "=r"(r1), "=r"(r2), "=r"(r3) : "r"(addr));
}

// ================= fp16 HMMA GEMM (KT=64, fragment-permuted A) ===============
// D[o, p] = sum_k W[o][k] * X[k][p].  M=128 o, N=128 p, K-chunk 64 (4 k16 steps)
// stage: A 16384 B (fragment order) + B 64 rows x 272 B = 17408 B -> 33792 B
#define STAGES    3
#define KT        64
#define B_PITCH   272
#define B_PITCH_H 136
#define STAGE_B   33792
#define SMEM_BYTES (STAGES * STAGE_B)

// MODE: 1 = +bias + fp16 res(xh), out fp16 (proj -> x2h)
//       3 = +bias + fp16 res(x2h), out fp32 (fc2 -> final)
//       4 = LN-fold via global mu/iv, out fp16 (qkv)
//       5 = LN-fold via in-CTA stats + GELU, out fp16 (fc1)
template<int MODE>
__global__ void __launch_bounds__(256, 2)
hgemm(const uint4* __restrict__ Wp, const __half* __restrict__ X,
      const float* __restrict__ bias, const __half* __restrict__ resh,
      float* __restrict__ out, __half* __restrict__ outh, int O, int K,
      const float* __restrict__ sarr,
      const float* __restrict__ mu, const float* __restrict__ inv)
{
    extern __shared__ float smf[];
    char* smc = reinterpret_cast<char*>(smf);
    const uint32_t sb = smem_u32(smf);
    const int tid  = threadIdx.x;
    const int wid  = tid >> 5;
    const int lane = tid & 31;
    const int r = lane >> 2;
    const int c = lane & 3;
    const int warp_m = (wid >> 2) * 64;
    const int warp_n = (wid & 3) * 32;
    const int mb0 = warp_m >> 4;

    const int b  = blockIdx.z;
    const int n0 = blockIdx.x * 128;
    const int m0 = blockIdx.y * 128;
    const __half* Xb = X + (size_t)b * K * HWP;
    float*  Ob  = (MODE == 3) ? out + (size_t)b * O * HWP : nullptr;
    __half* Obh = (MODE != 3) ? outh + (size_t)b * O * HWP : nullptr;
    const __half* Rbh = (MODE == 1 || MODE == 3) ? resh + (size_t)b * O * HWP : nullptr;

    const int mvalid = (O - m0 < 128) ? (O - m0) : 128;
    const int rows_w = mvalid - warp_m;

    const int NC   = (K + KT - 1) / KT;
    const int Kc32 = 2 * NC;

    auto load_stage = [&](int stage, int ch) {
        uint32_t a_base = sb + stage * STAGE_B;
        uint32_t b_base = a_base + 16384;
        const uint4* wsrc = Wp + ((size_t)blockIdx.y * Kc32 + 2 * ch) * 512;
        #pragma unroll
        for (int i = 0; i < 4; ++i) {               // A: 1024 x 16B contiguous
            int slot = tid + i * 256;
            cp16(a_base + slot * 16, wsrc + slot, true);
        }
        int k0 = ch * KT;
        #pragma unroll
        for (int i = 0; i < 4; ++i) {               // B: 64 rows x 16 x 16B
            int slot = tid + i * 256;
            int kr = slot >> 4, pc = slot & 15;
            int k = k0 + kr;
            bool v = (k < K);
            cp16(b_base + kr * B_PITCH + pc * 16,
                 v ? (const void*)(Xb + (size_t)k * HWP + n0 + pc * 8) : (const void*)Xb, v);
        }
    };

    float acc[4][4][4];
    #pragma unroll
    for (int i = 0; i < 4; ++i)
        #pragma unroll
        for (int j = 0; j < 4; ++j)
            #pragma unroll
            for (int t = 0; t < 4; ++t) acc[i][j][t] = 0.f;

    float psum[4] = {0.f, 0.f, 0.f, 0.f};
    float psq [4] = {0.f, 0.f, 0.f, 0.f};

    load_stage(0, 0);           CP_COMMIT();
    if (NC > 1) load_stage(1, 1);
    CP_COMMIT();

    for (int ch = 0; ch < NC; ++ch) {
        CP_WAIT1();
        __syncthreads();

        int ld = ch + 2;
        if (ld < NC) load_stage(ld % STAGES, ld);
        CP_COMMIT();

        const uint32_t stoff = (uint32_t)((ch % STAGES) * STAGE_B);

        if (rows_w > 0) {
            #pragma unroll
            for (int ks = 0; ks < 4; ++ks) {
                uint32_t af[4][4];
                #pragma unroll
                for (int mt = 0; mt < 4; ++mt) {
                    if (mt * 16 >= rows_w) continue;
                    uint4 v = *reinterpret_cast<const uint4*>(
                        smc + stoff +
                        (((ks >> 1) * 512) + ((ks & 1) * 256) + (mb0 + mt) * 32 + lane) * 16);
                    af[mt][0] = v.x; af[mt][1] = v.y;
                    af[mt][2] = v.z; af[mt][3] = v.w;
                }
                uint32_t bf[8];
                int rl = ks * 16 + (lane & 15);
                uint32_t baddr = sb + stoff + 16384 + rl * B_PITCH
                               + (warp_n + ((lane >> 4) << 3)) * 2;
                ldmx4t(bf[0], bf[1], bf[2], bf[3], baddr);
                ldmx4t(bf[4], bf[5], bf[6], bf[7], baddr + 32);
                #pragma unroll
                for (int mt = 0; mt < 4; ++mt) {
                    if (mt * 16 >= rows_w) continue;
                    #pragma unroll
                    for (int nt = 0; nt < 4; ++nt)
                        mma_f16(acc[mt][nt], af[mt], bf + nt * 2);
                }
            }
        }

        if (MODE == 5) {
            const __half* Bsh = reinterpret_cast<const __half*>(smc + stoff + 16384);
            #pragma unroll
            for (int i = 0; i < 8; ++i) {
                int kr = (tid >> 5) + 8 * i;
                const __half2* hp = reinterpret_cast<const __half2*>(
                    Bsh + kr * B_PITCH_H + (tid & 31) * 4);
                float2 f0 = __half22float2(hp[0]);
                float2 f1 = __half22float2(hp[1]);
                psum[0] += f0.x; psq[0] = fmaf(f0.x, f0.x, psq[0]);
                psum[1] += f0.y; psq[1] = fmaf(f0.y, f0.y, psq[1]);
                psum[2] += f1.x; psq[2] = fmaf(f1.x, f1.x, psq[2]);
                psum[3] += f1.y; psq[3] = fmaf(f1.y, f1.y, psq[3]);
            }
        }
    }

    if (MODE == 5) {
        CP_WAIT0();
        __syncthreads();
        int wg = tid >> 5, pxb = (tid & 31) * 4;
        #pragma unroll
        for (int j = 0; j < 4; ++j) {
            smf[wg * 128 + pxb + j]        = psum[j];
            smf[1024 + wg * 128 + pxb + j] = psq[j];
        }
        __syncthreads();
        if (tid < 128) {
            float s = 0.f, q = 0.f;
            #pragma unroll
            for (int w = 0; w < 8; ++w) {
                s += smf[w * 128 + tid];
                q += smf[1024 + w * 128 + tid];
            }
            float m  = s * (1.0f / CC);
            float iv = rsqrtf(q * (1.0f / CC) - m * m + 1e-5f);
            smf[2048 + tid] = m;
            smf[2176 + tid] = iv;
        }
        __syncthreads();
    }

    // ---- epilogue ----
    float2 m2[4], i2[4];
    if (MODE == 4) {
        const float* muB = mu  + (size_t)b * HWP + n0;
        const float* ivB = inv + (size_t)b * HWP + n0;
        #pragma unroll
        for (int nt = 0; nt < 4; ++nt) {
            int p = warp_n + nt * 8 + c * 2;
            m2[nt] = *reinterpret_cast<const float2*>(muB + p);
            i2[nt] = *reinterpret_cast<const float2*>(ivB + p);
        }
    }
    if (MODE == 5) {
        #pragma unroll
        for (int nt = 0; nt < 4; ++nt) {
            int p = warp_n + nt * 8 + c * 2;
            m2[nt] = *reinterpret_cast<const float2*>(smf + 2048 + p);
            i2[nt] = *reinterpret_cast<const float2*>(smf + 2176 + p);
        }
    }
    #pragma unroll
    for (int mt = 0; mt < 4; ++mt) {
        #pragma unroll
        for (int half = 0; half < 2; ++half) {
            int o = m0 + warp_m + mt * 16 + half * 8 + r;
            if (o >= O) continue;
            float bv = bias[o];
            float so = (MODE >= 4) ? sarr[o] : 0.f;
            #pragma unroll
            for (int nt = 0; nt < 4; ++nt) {
                int p = n0 + warp_n + nt * 8 + c * 2;
                float v0 = acc[mt][nt][half * 2 + 0];
                float v1 = acc[mt][nt][half * 2 + 1];
                if (MODE == 1 || MODE == 3) {
                    float2 rv = __half22float2(
                        *reinterpret_cast<const __half2*>(Rbh + (size_t)o * HWP + p));
                    v0 += bv + rv.x; v1 += bv + rv.y;
                } else {
                    v0 = i2[nt].x * (v0 - m2[nt].x * so) + bv;
                    v1 = i2[nt].y * (v1 - m2[nt].y * so) + bv;
                    if (MODE == 5) {
                        v0 = 0.5f * v0 * (1.0f + erff(v0 * 0.70710678118654752f));
                        v1 = 0.5f * v1 * (1.0f + erff(v1 * 0.70710678118654752f));
                    }
                }
                if (MODE == 3)
                    *reinterpret_cast<float2*>(Ob + (size_t)o * HWP + p)
                        = make_float2(v0, v1);
                else
                    *reinterpret_cast<__half2*>(Obh + (size_t)o * HWP + p)
                        = __floats2half2_rn(v0, v1);
            }
        }
    }
}

// ================= mega-prep (one launch) ====================================
#define XH_CTAS  (BB * CC * HWP / (256 * 8))           // 12544
#define P1_CTAS  (MT_QKV * KC32_C * 2)                 // 280
#define P2_CTAS  (MT_C   * KC32_C * 2)                 // 112
#define P3_CTAS  (MT_HID * KC32_C * 2)                 // 364
#define P4_CTAS  (MT_C   * KC32_HID * 2)               // 400
#define SCB1_CTAS ((C3  * 32 + 255) / 256)
#define SCB2_CTAS ((HID * 32 + 255) / 256)
#define STAT_CTAS (BB * HWP / 256)
#define PREP_CTAS (XH_CTAS + P1_CTAS + P2_CTAS + P3_CTAS + P4_CTAS + \
                   SCB1_CTAS + SCB2_CTAS + STAT_CTAS)

struct PrepArgs {
    const float *qkv_w, *proj_w, *fc1_w, *fc2_w;
    const float *ln1_g, *ln1_b, *ln2_g, *ln2_b;
    const float *qkv_b, *fc1_b;
    const float *x;
    __half *xh;
    uint4 *w1p, *wpp, *w2p, *w3p;
    float *s1, *cb1, *s2, *cb2;
    float *mu1, *iv1;
};

__device__ __forceinline__ void do_perm_h(
    const float* __restrict__ W, const float* __restrict__ g,
    uint4* __restrict__ Wp, int O, int K, int Kc32, size_t gid)
{
    int lane = (int)(gid & 31);
    int mb   = (int)((gid >> 5) & 7);
    int ks   = (int)((gid >> 8) & 1);
    size_t t = gid >> 9;
    int ch = (int)(t % Kc32);
    int mt = (int)(t / Kc32);
    int r = lane >> 2, c = lane & 3;
    int row0 = mt * 128 + mb * 16 + r, row1 = row0 + 8;
    int k0 = ch * 32 + ks * 16 + 2 * c;
    float w00=0.f,w01=0.f,w02=0.f,w03=0.f,w10=0.f,w11=0.f,w12=0.f,w13=0.f;
    auto ld = [&](int rr, int kk) -> float {
        return (kk < K) ? W[(size_t)rr * K + kk] * (g ? g[kk] : 1.f) : 0.f;
    };
    if (row0 < O) { w00=ld(row0,k0); w01=ld(row0,k0+1); w02=ld(row0,k0+8); w03=ld(row0,k0+9); }
    if (row1 < O) { w10=ld(row1,k0); w11=ld(row1,k0+1); w12=ld(row1,k0+8); w13=ld(row1,k0+9); }
    uint4 o;
    o.x = pack2(w00, w01); o.y = pack2(w10, w11);
    o.z = pack2(w02, w03); o.w = pack2(w12, w13);
    Wp[gid] = o;
}

__device__ __forceinline__ void do_scb(
    const float* __restrict__ W, const float* __restrict__ g,
    const float* __restrict__ bta, const float* __restrict__ bias,
    float* __restrict__ sarr, float* __restrict__ cb, int O, int K,
    int idx, int lane)
{
    int w = idx >> 5;
    if (w >= O) return;
    float ss = 0.f, bs = 0.f;
    for (int k = lane; k < K; k += 32) {
        float wv = W[(size_t)w * K + k];
        ss += wv * g[k];
        bs += wv * bta[k];
    }
    #pragma unroll
    for (int off = 16; off; off >>= 1) {
        ss += __shfl_xor_sync(0xFFFFFFFFu, ss, off);
        bs += __shfl_xor_sync(0xFFFFFFFFu, bs, off);
    }
    if (lane == 0) { sarr[w] = ss; cb[w] = bias[w] + bs; }
}

__global__ void __launch_bounds__(256) mega_prep(PrepArgs a)
{
    int cta = blockIdx.x;
    int tid = threadIdx.x;
    if (cta < XH_CTAS) {   // x -> fp16
        size_t i0 = ((size_t)cta * 256 + tid) * 8;
        float4 f0 = *reinterpret_cast<const float4*>(a.x + i0);
        float4 f1 = *reinterpret_cast<const float4*>(a.x + i0 + 4);
        uint4 o;
        o.x = pack2(f0.x, f0.y); o.y = pack2(f0.z, f0.w);
        o.z = pack2(f1.x, f1.y); o.w = pack2(f1.z, f1.w);
        *reinterpret_cast<uint4*>(a.xh + i0) = o;
        return;
    }
    cta -= XH_CTAS;
    if (cta < P1_CTAS) { do_perm_h(a.qkv_w, a.ln1_g, a.w1p, C3, CC, KC32_C, (size_t)cta*256+tid); return; }
    cta -= P1_CTAS;
    if (cta < P2_CTAS) { do_perm_h(a.proj_w, nullptr, a.wpp, CC, CC, KC32_C, (size_t)cta*256+tid); return; }
    cta -= P2_CTAS;
    if (cta < P3_CTAS) { do_perm_h(a.fc1_w, a.ln2_g, a.w2p, HID, CC, KC32_C, (size_t)cta*256+tid); return; }
    cta -= P3_CTAS;
    if (cta < P4_CTAS) { do_perm_h(a.fc2_w, nullptr, a.w3p, CC, HID, KC32_HID, (size_t)cta*256+tid); return; }
    cta -= P4_CTAS;
    if (cta < SCB1_CTAS) { do_scb(a.qkv_w, a.ln1_g, a.ln1_b, a.qkv_b, a.s1, a.cb1, C3, CC, cta*256+tid, tid&31); return; }
    cta -= SCB1_CTAS;
    if (cta < SCB2_CTAS) { do_scb(a.fc1_w, a.ln2_g, a.ln2_b, a.fc1_b, a.s2, a.cb2, HID, CC, cta*256+tid, tid&31); return; }
    cta -= SCB2_CTAS;
    {   // LN1 stats (fp32 x)
        int idx = cta * 256 + tid;
        int b = idx / HWP;
        int p = idx - b * HWP;
        const float* xb = a.x + (size_t)b * CC * HWP + p;
        float s = 0.f, s2 = 0.f;
        #pragma unroll 8
        for (int c = 0; c < CC; c++) {
            float v = xb[(size_t)c * HWP];
            s += v; s2 += v * v;
        }
        float m  = s * (1.0f / CC);
        float var = s2 * (1.0f / CC) - m * m;
        a.mu1[idx] = m;
        a.iv1[idx] = rsqrtf(var + 1e-5f);
    }
}

// ---------------- attention + softmax (fp16 in/out, smem-staged writes) ------
#define ATILE 256
#define ATT_SMEM (ATILE * HD * 2)     // 25088 bytes

__global__ void __launch_bounds__(256) attn_kernel(
    const __half* __restrict__ qkv, const float* __restrict__ rel_bias,
    __half* __restrict__ out)
{
    extern __shared__ __half smh[];
    const int tid = threadIdx.x;
    int tile = blockIdx.x;
    int p0   = (tile & 15) * ATILE;
    int bh   = tile >> 4;
    int head = bh & (NH - 1);
    int b    = bh >> 3;
    int p    = p0 + tid;

    const __half* base = qkv + (size_t)b * C3 * HWP;
    const __half* qp = base + (size_t)(head * HD) * HWP + p;
    const __half* kp = base + (size_t)(CC + head * HD) * HWP + p;
    const __half* vp = base + (size_t)(2 * CC + head * HD) * HWP + p;
    const float scale = 0.14285714285714285f;   // 49^-0.5

    float s[HD];
    float mx = -INFINITY;
    #pragma unroll
    for (int d = 0; d < HD; d++) {
        float sv = __half2float(qp[(size_t)d * HWP]) * scale
                 * __half2float(kp[(size_t)d * HWP]) + rel_bias[head * HD + d];
        s[d] = sv;
        mx = fmaxf(mx, sv);
    }
    float sum = 0.f;
    #pragma unroll
    for (int d = 0; d < HD; d++) {
        float e = __expf(s[d] - mx);
        s[d] = e;
        sum += e;
    }
    float inv = 1.0f / sum;
    __half* st = smh + tid * HD;
    #pragma unroll
    for (int d = 0; d < HD; d++) {
        st[d] = __float2half_rn(s[d] * inv * __half2float(vp[(size_t)d * HWP]));
    }
    __syncthreads();

    uint4* dst = reinterpret_cast<uint4*>(
        out + (size_t)b * CC * HWP + (size_t)head * HWP * HD + (size_t)p0 * HD);
    const uint4* src = reinterpret_cast<const uint4*>(smh);
    #pragma unroll
    for (int i = tid; i < ATILE * HD / 8; i += 256)
        dst[i] = src[i];
}

// ---------------- launch ----------------
extern "C" void kernel_launch(void* const* d_in, const int* in_sizes, int n_in,
                              void* d_out, int out_size)
{
    const float* x      = (const float*)d_in[0];
    const float* ln1_g  = (const float*)d_in[1];
    const float* ln1_b  = (const float*)d_in[2];
    const float* qkv_w  = (const float*)d_in[3];
    const float* qkv_b  = (const float*)d_in[4];
    const float* relb   = (const float*)d_in[5];
    const float* proj_w = (const float*)d_in[6];
    const float* proj_b = (const float*)d_in[7];
    const float* ln2_g  = (const float*)d_in[8];
    const float* ln2_b  = (const float*)d_in[9];
    const float* fc1_w  = (const float*)d_in[10];
    const float* fc1_b  = (const float*)d_in[11];
    const float* fc2_w  = (const float*)d_in[12];
    const float* fc2_b  = (const float*)d_in[13];
    float* outp = (float*)d_out;

    __half *xh, *qkv, *attn, *x2h, *mlp;
    uint4 *w1p, *wpp, *w2p, *w3p;
    float *s1, *cb1, *s2, *cb2, *mu1, *iv1;
    cudaGetSymbolAddress((void**)&xh,   g_xh);
    cudaGetSymbolAddress((void**)&qkv,  g_qkv);
    cudaGetSymbolAddress((void**)&attn, g_attn);
    cudaGetSymbolAddress((void**)&x2h,  g_x2h);
    cudaGetSymbolAddress((void**)&mlp,  g_mlp);
    cudaGetSymbolAddress((void**)&w1p,  g_w1p);
    cudaGetSymbolAddress((void**)&wpp,  g_wpp);
    cudaGetSymbolAddress((void**)&w2p,  g_w2p);
    cudaGetSymbolAddress((void**)&w3p,  g_w3p);
    cudaGetSymbolAddress((void**)&s1,   g_s1);
    cudaGetSymbolAddress((void**)&cb1,  g_cb1);
    cudaGetSymbolAddress((void**)&s2,   g_s2);
    cudaGetSymbolAddress((void**)&cb2,  g_cb2);
    cudaGetSymbolAddress((void**)&mu1,  g_mu1);
    cudaGetSymbolAddress((void**)&iv1,  g_iv1);

    cudaFuncSetAttribute(hgemm<1>, cudaFuncAttributeMaxDynamicSharedMemorySize, SMEM_BYTES);
    cudaFuncSetAttribute(hgemm<3>, cudaFuncAttributeMaxDynamicSharedMemorySize, SMEM_BYTES);
    cudaFuncSetAttribute(hgemm<4>, cudaFuncAttributeMaxDynamicSharedMemorySize, SMEM_BYTES);
    cudaFuncSetAttribute(hgemm<5>, cudaFuncAttributeMaxDynamicSharedMemorySize, SMEM_BYTES);

    // 0) ONE prep launch
    {
        PrepArgs a;
        a.qkv_w = qkv_w; a.proj_w = proj_w; a.fc1_w = fc1_w; a.fc2_w = fc2_w;
        a.ln1_g = ln1_g; a.ln1_b = ln1_b; a.ln2_g = ln2_g; a.ln2_b = ln2_b;
        a.qkv_b = qkv_b; a.fc1_b = fc1_b; a.x = x; a.xh = xh;
        a.w1p = w1p; a.wpp = wpp; a.w2p = w2p; a.w3p = w3p;
        a.s1 = s1; a.cb1 = cb1; a.s2 = s2; a.cb2 = cb2;
        a.mu1 = mu1; a.iv1 = iv1;
        mega_prep<<<PREP_CTAS, 256>>>(a);
    }

    // 1) qkv GEMM with fused LN1 (B = xh) -> qkv fp16
    {
        dim3 grid(HWP / 128, MT_QKV, BB);
        hgemm<4><<<grid, 256, SMEM_BYTES>>>(w1p, xh, cb1, nullptr,
                                            nullptr, qkv, C3, CC, s1, mu1, iv1);
    }

    // 2) attention + softmax (fp16)
    attn_kernel<<<BB * NH * (HWP / ATILE), 256, ATT_SMEM>>>(qkv, relb, attn);

    // 3) proj GEMM + bias + fp16 shortcut(xh) -> x2h
    {
        dim3 grid(HWP / 128, MT_C, BB);
        hgemm<1><<<grid, 256, SMEM_BYTES>>>(wpp, attn, proj_b, xh,
                                            nullptr, x2h, CC, CC, nullptr, nullptr, nullptr);
    }

    // 4) fc1 GEMM with in-CTA LN2 stats + fold + GELU (B = x2h) -> mlp fp16
    {
        dim3 grid(HWP / 128, MT_HID, BB);
        hgemm<5><<<grid, 256, SMEM_BYTES>>>(w2p, x2h, cb2, nullptr,
                                            nullptr, mlp, HID, CC, s2, nullptr, nullptr);
    }

    // 5) fc2 GEMM + bias + fp16 residual(x2h) -> out fp32
    {
        dim3 grid(HWP / 128, MT_C, BB);
        hgemm<3><<<grid, 256, SMEM_BYTES>>>(w3p, mlp, fc2_b, x2h,
                                            outp, nullptr, CC, HID, nullptr, nullptr, nullptr);
    }
}

// round 13
// speedup vs baseline: 1.0299x; 1.0299x over previous
#include <cuda_runtime.h>
#include <cuda_fp16.h>
#include <math.h>
#include <stdint.h>

// Problem dims (fixed by the dataset)
#define BB   16
#define CC   392
#define HWP  4096          // 64*64 pixels
#define NH   8
#define HD   49            // head dim
#define HID  1568          // 4*C
#define C3   1176          // 3*C

#define KT   32
#define KC_C    13
#define KC_HID  49
#define MT_QKV  10
#define MT_C    4
#define MT_HID  13

// ---------------- scratch (static device, no allocs) ----------------
__device__ __half g_xh  [(size_t)BB * CC  * HWP];   // fp16 copy of x
__device__ __half g_qkv [(size_t)BB * C3  * HWP];
__device__ __half g_attn[(size_t)BB * CC  * HWP];
__device__ __half g_x2h [(size_t)BB * CC  * HWP];   // fp16 residual trunk
__device__ __half g_mlp [(size_t)BB * HID * HWP];
// fragment-permuted fp16 weights: [mtile][kchunk][kstep2][mb8][lane32] x uint4
__device__ uint4 g_w1p [(size_t)MT_QKV * KC_C   * 512];
__device__ uint4 g_wpp [(size_t)MT_C   * KC_C   * 512];
__device__ uint4 g_w2p [(size_t)MT_HID * KC_C   * 512];
__device__ uint4 g_w3p [(size_t)MT_C   * KC_HID * 512];
__device__ float g_s1  [C3],  g_cb1[C3];
__device__ float g_s2  [HID], g_cb2[HID];
__device__ float g_mu1 [(size_t)BB * HWP], g_iv1[(size_t)BB * HWP];

// ================= helpers =================
__device__ __forceinline__ uint32_t smem_u32(const void* p) {
    uint32_t a;
    asm("{ .reg .u64 t; cvta.to.shared.u64 t, %1; cvt.u32.u64 %0, t; }"
        : "=r"(a) : "l"(p));
    return a;
}
__device__ __forceinline__ void cp16(uint32_t saddr, const void* g, bool valid) {
    unsigned long long ga;
    asm("cvta.to.global.u64 %0, %1;" : "=l"(ga) : "l"(g));
    int sz = valid ? 16 : 0;
    asm volatile("cp.async.cg.shared.global [%0], [%1], 16, %2;"
                 :: "r"(saddr), "l"(ga), "r"(sz));
}
#define CP_COMMIT() asm volatile("cp.async.commit_group;" ::: "memory")
#define CP_WAIT1()  asm volatile("cp.async.wait_group 1;" ::: "memory")
#define CP_WAIT0()  asm volatile("cp.async.wait_group 0;" ::: "memory")

__device__ __forceinline__ uint32_t pack2(float a, float b) {
    __half2 h = __floats2half2_rn(a, b);
    return *reinterpret_cast<uint32_t*>(&h);
}
__device__ __forceinline__ void mma_f16(float* d, const uint32_t* a, const uint32_t* b) {
    asm volatile(
        "mma.sync.aligned.m16n8k16.row.col.f32.f16.f16.f32 "
        "{%0,%1,%2,%3}, {%4,%5,%6,%7}, {%8,%9}, {%0,%1,%2,%3};"
        : "+f"(d[0]), "+f"(d[1]), "+f"(d[2]), "+f"(d[3])
        : "r"(a[0]), "r"(a[1]), "r"(a[2]), "r"(a[3]), "r"(b[0]), "r"(b[1]));
}
__device__ __forceinline__ void ldmx4t(uint32_t& r0, uint32_t& r1,
                                       uint32_t& r2, uint32_t& r3, uint32_t addr) {
    asm volatile("ldmatrix.sync.aligned.m8n8.x4.trans.shared.b16 {%0,%1,%2,%3}, [%4];"
        : "=r"(r0), "=r"(r1), "=r"(r2), "=r"(r3) : "r"(addr));
}

// ================= fp16 HMMA GEMM (KT=32, fragment-permuted A) ===============
// D[o, p] = sum_k W[o][k] * X[k][p].  M=128 o, N=128 p, K-chunk 32 (2 k16 steps)
// stage: A 8192 B (fragment order) + B 32 rows x 272 B = 8704 B -> 16896 B
#define STAGES    3
#define B_PITCH   272
#define B_PITCH_H 136
#define STAGE_B   16896
#define SMEM_BYTES (STAGES * STAGE_B)

// MODE: 1 = +bias + fp16 res(xh), out fp16 (proj -> x2h)
//       3 = +bias + fp16 res(x2h), out fp32 (fc2 -> final)
//       4 = LN-fold via global mu/iv, out fp16 (qkv)
//       5 = LN-fold via in-CTA stats + GELU, out fp16 (fc1)
template<int MODE>
__global__ void __launch_bounds__(256, 2)
hgemm(const uint4* __restrict__ Wp, const __half* __restrict__ X,
      const float* __restrict__ bias, const __half* __restrict__ resh,
      float* __restrict__ out, __half* __restrict__ outh, int O, int K,
      const float* __restrict__ sarr,
      const float* __restrict__ mu, const float* __restrict__ inv)
{
    extern __shared__ float smf[];
    char* smc = reinterpret_cast<char*>(smf);
    const uint32_t sb = smem_u32(smf);
    const int tid  = threadIdx.x;
    const int wid  = tid >> 5;
    const int lane = tid & 31;
    const int r = lane >> 2;
    const int c = lane & 3;
    const int warp_m = (wid >> 2) * 64;
    const int warp_n = (wid & 3) * 32;
    const int mb0 = warp_m >> 4;

    const int b  = blockIdx.z;
    const int n0 = blockIdx.x * 128;
    const int m0 = blockIdx.y * 128;
    const __half* Xb = X + (size_t)b * K * HWP;
    float*  Ob  = (MODE == 3) ? out + (size_t)b * O * HWP : nullptr;
    __half* Obh = (MODE != 3) ? outh + (size_t)b * O * HWP : nullptr;
    const __half* Rbh = (MODE == 1 || MODE == 3) ? resh + (size_t)b * O * HWP : nullptr;

    const int mvalid = (O - m0 < 128) ? (O - m0) : 128;
    const int rows_w = mvalid - warp_m;

    const int NC = (K + KT - 1) / KT;

    auto load_stage = [&](int stage, int ch) {
        uint32_t a_base = sb + stage * STAGE_B;
        uint32_t b_base = a_base + 8192;
        const uint4* wsrc = Wp + ((size_t)blockIdx.y * NC + ch) * 512;
        #pragma unroll
        for (int i = 0; i < 2; ++i) {               // A: 512 x 16B contiguous
            int slot = tid + i * 256;
            cp16(a_base + slot * 16, wsrc + slot, true);
        }
        int k0 = ch * KT;
        #pragma unroll
        for (int i = 0; i < 2; ++i) {               // B: 32 rows x 16 x 16B
            int slot = tid + i * 256;
            int kr = slot >> 4, pc = slot & 15;
            int k = k0 + kr;
            bool v = (k < K);
            cp16(b_base + kr * B_PITCH + pc * 16,
                 v ? (const void*)(Xb + (size_t)k * HWP + n0 + pc * 8) : (const void*)Xb, v);
        }
    };

    float acc[4][4][4];
    #pragma unroll
    for (int i = 0; i < 4; ++i)
        #pragma unroll
        for (int j = 0; j < 4; ++j)
            #pragma unroll
            for (int t = 0; t < 4; ++t) acc[i][j][t] = 0.f;

    float psum[4] = {0.f, 0.f, 0.f, 0.f};
    float psq [4] = {0.f, 0.f, 0.f, 0.f};

    load_stage(0, 0);           CP_COMMIT();
    if (NC > 1) load_stage(1, 1);
    CP_COMMIT();

    for (int ch = 0; ch < NC; ++ch) {
        CP_WAIT1();
        __syncthreads();

        int ld = ch + 2;
        if (ld < NC) load_stage(ld % STAGES, ld);
        CP_COMMIT();

        const uint32_t stoff = (uint32_t)((ch % STAGES) * STAGE_B);

        if (rows_w > 0) {
            #pragma unroll
            for (int ks = 0; ks < 2; ++ks) {
                uint32_t af[4][4];
                #pragma unroll
                for (int mt = 0; mt < 4; ++mt) {
                    if (mt * 16 >= rows_w) continue;
                    uint4 v = *reinterpret_cast<const uint4*>(
                        smc + stoff + (ks * 256 + (mb0 + mt) * 32 + lane) * 16);
                    af[mt][0] = v.x; af[mt][1] = v.y;
                    af[mt][2] = v.z; af[mt][3] = v.w;
                }
                uint32_t bf[8];
                int rl = ks * 16 + (lane & 15);
                uint32_t baddr = sb + stoff + 8192 + rl * B_PITCH
                               + (warp_n + ((lane >> 4) << 3)) * 2;
                ldmx4t(bf[0], bf[1], bf[2], bf[3], baddr);
                ldmx4t(bf[4], bf[5], bf[6], bf[7], baddr + 32);
                #pragma unroll
                for (int mt = 0; mt < 4; ++mt) {
                    if (mt * 16 >= rows_w) continue;
                    #pragma unroll
                    for (int nt = 0; nt < 4; ++nt)
                        mma_f16(acc[mt][nt], af[mt], bf + nt * 2);
                }
            }
        }

        if (MODE == 5) {
            const __half* Bsh = reinterpret_cast<const __half*>(smc + stoff + 8192);
            #pragma unroll
            for (int i = 0; i < 4; ++i) {
                int kr = (tid >> 5) + 8 * i;
                const __half2* hp = reinterpret_cast<const __half2*>(
                    Bsh + kr * B_PITCH_H + (tid & 31) * 4);
                float2 f0 = __half22float2(hp[0]);
                float2 f1 = __half22float2(hp[1]);
                psum[0] += f0.x; psq[0] = fmaf(f0.x, f0.x, psq[0]);
                psum[1] += f0.y; psq[1] = fmaf(f0.y, f0.y, psq[1]);
                psum[2] += f1.x; psq[2] = fmaf(f1.x, f1.x, psq[2]);
                psum[3] += f1.y; psq[3] = fmaf(f1.y, f1.y, psq[3]);
            }
        }
    }

    if (MODE == 5) {
        CP_WAIT0();
        __syncthreads();
        int wg = tid >> 5, pxb = (tid & 31) * 4;
        #pragma unroll
        for (int j = 0; j < 4; ++j) {
            smf[wg * 128 + pxb + j]        = psum[j];
            smf[1024 + wg * 128 + pxb + j] = psq[j];
        }
        __syncthreads();
        if (tid < 128) {
            float s = 0.f, q = 0.f;
            #pragma unroll
            for (int w = 0; w < 8; ++w) {
                s += smf[w * 128 + tid];
                q += smf[1024 + w * 128 + tid];
            }
            float m  = s * (1.0f / CC);
            float iv = rsqrtf(q * (1.0f / CC) - m * m + 1e-5f);
            smf[2048 + tid] = m;
            smf[2176 + tid] = iv;
        }
        __syncthreads();
    }

    // ---- epilogue ----
    float2 m2[4], i2[4];
    if (MODE == 4) {
        const float* muB = mu  + (size_t)b * HWP + n0;
        const float* ivB = inv + (size_t)b * HWP + n0;
        #pragma unroll
        for (int nt = 0; nt < 4; ++nt) {
            int p = warp_n + nt * 8 + c * 2;
            m2[nt] = *reinterpret_cast<const float2*>(muB + p);
            i2[nt] = *reinterpret_cast<const float2*>(ivB + p);
        }
    }
    if (MODE == 5) {
        #pragma unroll
        for (int nt = 0; nt < 4; ++nt) {
            int p = warp_n + nt * 8 + c * 2;
            m2[nt] = *reinterpret_cast<const float2*>(smf + 2048 + p);
            i2[nt] = *reinterpret_cast<const float2*>(smf + 2176 + p);
        }
    }
    #pragma unroll
    for (int mt = 0; mt < 4; ++mt) {
        #pragma unroll
        for (int half = 0; half < 2; ++half) {
            int o = m0 + warp_m + mt * 16 + half * 8 + r;
            if (o >= O) continue;
            float bv = bias[o];
            float so = (MODE >= 4) ? sarr[o] : 0.f;
            #pragma unroll
            for (int nt = 0; nt < 4; ++nt) {
                int p = n0 + warp_n + nt * 8 + c * 2;
                float v0 = acc[mt][nt][half * 2 + 0];
                float v1 = acc[mt][nt][half * 2 + 1];
                if (MODE == 1 || MODE == 3) {
                    float2 rv = __half22float2(
                        *reinterpret_cast<const __half2*>(Rbh + (size_t)o * HWP + p));
                    v0 += bv + rv.x; v1 += bv + rv.y;
                } else {
                    v0 = i2[nt].x * (v0 - m2[nt].x * so) + bv;
                    v1 = i2[nt].y * (v1 - m2[nt].y * so) + bv;
                    if (MODE == 5) {
                        v0 = 0.5f * v0 * (1.0f + erff(v0 * 0.70710678118654752f));
                        v1 = 0.5f * v1 * (1.0f + erff(v1 * 0.70710678118654752f));
                    }
                }
                if (MODE == 3)
                    *reinterpret_cast<float2*>(Ob + (size_t)o * HWP + p)
                        = make_float2(v0, v1);
                else
                    *reinterpret_cast<__half2*>(Obh + (size_t)o * HWP + p)
                        = __floats2half2_rn(v0, v1);
            }
        }
    }
}

// ================= mega-prep (one launch) ====================================
#define XH_CTAS  (BB * CC * HWP / (256 * 8))     // 12544
#define P1_CTAS  (MT_QKV * KC_C * 2)             // 260
#define P2_CTAS  (MT_C   * KC_C * 2)             // 104
#define P3_CTAS  (MT_HID * KC_C * 2)             // 338
#define P4_CTAS  (MT_C   * KC_HID * 2)           // 392
#define SCB1_CTAS ((C3  * 32 + 255) / 256)
#define SCB2_CTAS ((HID * 32 + 255) / 256)
#define STAT_CTAS (BB * HWP / 256)
#define PREP_CTAS (XH_CTAS + P1_CTAS + P2_CTAS + P3_CTAS + P4_CTAS + \
                   SCB1_CTAS + SCB2_CTAS + STAT_CTAS)

struct PrepArgs {
    const float *qkv_w, *proj_w, *fc1_w, *fc2_w;
    const float *ln1_g, *ln1_b, *ln2_g, *ln2_b;
    const float *qkv_b, *fc1_b;
    const float *x;
    __half *xh;
    uint4 *w1p, *wpp, *w2p, *w3p;
    float *s1, *cb1, *s2, *cb2;
    float *mu1, *iv1;
};

__device__ __forceinline__ void do_perm_h(
    const float* __restrict__ W, const float* __restrict__ g,
    uint4* __restrict__ Wp, int O, int K, int Kc, size_t gid)
{
    int lane = (int)(gid & 31);
    int mb   = (int)((gid >> 5) & 7);
    int ks   = (int)((gid >> 8) & 1);
    size_t t = gid >> 9;
    int ch = (int)(t % Kc);
    int mt = (int)(t / Kc);
    int r = lane >> 2, c = lane & 3;
    int row0 = mt * 128 + mb * 16 + r, row1 = row0 + 8;
    int k0 = ch * 32 + ks * 16 + 2 * c;
    float w00=0.f,w01=0.f,w02=0.f,w03=0.f,w10=0.f,w11=0.f,w12=0.f,w13=0.f;
    auto ld = [&](int rr, int kk) -> float {
        return (kk < K) ? W[(size_t)rr * K + kk] * (g ? g[kk] : 1.f) : 0.f;
    };
    if (row0 < O) { w00=ld(row0,k0); w01=ld(row0,k0+1); w02=ld(row0,k0+8); w03=ld(row0,k0+9); }
    if (row1 < O) { w10=ld(row1,k0); w11=ld(row1,k0+1); w12=ld(row1,k0+8); w13=ld(row1,k0+9); }
    uint4 o;
    o.x = pack2(w00, w01); o.y = pack2(w10, w11);
    o.z = pack2(w02, w03); o.w = pack2(w12, w13);
    Wp[gid] = o;
}

__device__ __forceinline__ void do_scb(
    const float* __restrict__ W, const float* __restrict__ g,
    const float* __restrict__ bta, const float* __restrict__ bias,
    float* __restrict__ sarr, float* __restrict__ cb, int O, int K,
    int idx, int lane)
{
    int w = idx >> 5;
    if (w >= O) return;
    float ss = 0.f, bs = 0.f;
    for (int k = lane; k < K; k += 32) {
        float wv = W[(size_t)w * K + k];
        ss += wv * g[k];
        bs += wv * bta[k];
    }
    #pragma unroll
    for (int off = 16; off; off >>= 1) {
        ss += __shfl_xor_sync(0xFFFFFFFFu, ss, off);
        bs += __shfl_xor_sync(0xFFFFFFFFu, bs, off);
    }
    if (lane == 0) { sarr[w] = ss; cb[w] = bias[w] + bs; }
}

__global__ void __launch_bounds__(256) mega_prep(PrepArgs a)
{
    int cta = blockIdx.x;
    int tid = threadIdx.x;
    if (cta < XH_CTAS) {   // x -> fp16
        size_t i0 = ((size_t)cta * 256 + tid) * 8;
        float4 f0 = *reinterpret_cast<const float4*>(a.x + i0);
        float4 f1 = *reinterpret_cast<const float4*>(a.x + i0 + 4);
        uint4 o;
        o.x = pack2(f0.x, f0.y); o.y = pack2(f0.z, f0.w);
        o.z = pack2(f1.x, f1.y); o.w = pack2(f1.z, f1.w);
        *reinterpret_cast<uint4*>(a.xh + i0) = o;
        return;
    }
    cta -= XH_CTAS;
    if (cta < P1_CTAS) { do_perm_h(a.qkv_w, a.ln1_g, a.w1p, C3, CC, KC_C, (size_t)cta*256+tid); return; }
    cta -= P1_CTAS;
    if (cta < P2_CTAS) { do_perm_h(a.proj_w, nullptr, a.wpp, CC, CC, KC_C, (size_t)cta*256+tid); return; }
    cta -= P2_CTAS;
    if (cta < P3_CTAS) { do_perm_h(a.fc1_w, a.ln2_g, a.w2p, HID, CC, KC_C, (size_t)cta*256+tid); return; }
    cta -= P3_CTAS;
    if (cta < P4_CTAS) { do_perm_h(a.fc2_w, nullptr, a.w3p, CC, HID, KC_HID, (size_t)cta*256+tid); return; }
    cta -= P4_CTAS;
    if (cta < SCB1_CTAS) { do_scb(a.qkv_w, a.ln1_g, a.ln1_b, a.qkv_b, a.s1, a.cb1, C3, CC, cta*256+tid, tid&31); return; }
    cta -= SCB1_CTAS;
    if (cta < SCB2_CTAS) { do_scb(a.fc1_w, a.ln2_g, a.ln2_b, a.fc1_b, a.s2, a.cb2, HID, CC, cta*256+tid, tid&31); return; }
    cta -= SCB2_CTAS;
    {   // LN1 stats (fp32 x)
        int idx = cta * 256 + tid;
        int b = idx / HWP;
        int p = idx - b * HWP;
        const float* xb = a.x + (size_t)b * CC * HWP + p;
        float s = 0.f, s2 = 0.f;
        #pragma unroll 8
        for (int c = 0; c < CC; c++) {
            float v = xb[(size_t)c * HWP];
            s += v; s2 += v * v;
        }
        float m  = s * (1.0f / CC);
        float var = s2 * (1.0f / CC) - m * m;
        a.mu1[idx] = m;
        a.iv1[idx] = rsqrtf(var + 1e-5f);
    }
}

// ---------------- attention + softmax (fp16 in/out, smem-staged writes) ------
#define ATILE 256
#define ATT_SMEM (ATILE * HD * 2)     // 25088 bytes

__global__ void __launch_bounds__(256) attn_kernel(
    const __half* __restrict__ qkv, const float* __restrict__ rel_bias,
    __half* __restrict__ out)
{
    extern __shared__ __half smh[];
    const int tid = threadIdx.x;
    int tile = blockIdx.x;
    int p0   = (tile & 15) * ATILE;
    int bh   = tile >> 4;
    int head = bh & (NH - 1);
    int b    = bh >> 3;
    int p    = p0 + tid;

    const __half* base = qkv + (size_t)b * C3 * HWP;
    const __half* qp = base + (size_t)(head * HD) * HWP + p;
    const __half* kp = base + (size_t)(CC + head * HD) * HWP + p;
    const __half* vp = base + (size_t)(2 * CC + head * HD) * HWP + p;
    const float scale = 0.14285714285714285f;   // 49^-0.5

    float s[HD];
    float mx = -INFINITY;
    #pragma unroll
    for (int d = 0; d < HD; d++) {
        float sv = __half2float(qp[(size_t)d * HWP]) * scale
                 * __half2float(kp[(size_t)d * HWP]) + rel_bias[head * HD + d];
        s[d] = sv;
        mx = fmaxf(mx, sv);
    }
    float sum = 0.f;
    #pragma unroll
    for (int d = 0; d < HD; d++) {
        float e = __expf(s[d] - mx);
        s[d] = e;
        sum += e;
    }
    float inv = 1.0f / sum;
    __half* st = smh + tid * HD;
    #pragma unroll
    for (int d = 0; d < HD; d++) {
        st[d] = __float2half_rn(s[d] * inv * __half2float(vp[(size_t)d * HWP]));
    }
    __syncthreads();

    uint4* dst = reinterpret_cast<uint4*>(
        out + (size_t)b * CC * HWP + (size_t)head * HWP * HD + (size_t)p0 * HD);
    const uint4* src = reinterpret_cast<const uint4*>(smh);
    #pragma unroll
    for (int i = tid; i < ATILE * HD / 8; i += 256)
        dst[i] = src[i];
}

// ---------------- launch ----------------
extern "C" void kernel_launch(void* const* d_in, const int* in_sizes, int n_in,
                              void* d_out, int out_size)
{
    const float* x      = (const float*)d_in[0];
    const float* ln1_g  = (const float*)d_in[1];
    const float* ln1_b  = (const float*)d_in[2];
    const float* qkv_w  = (const float*)d_in[3];
    const float* qkv_b  = (const float*)d_in[4];
    const float* relb   = (const float*)d_in[5];
    const float* proj_w = (const float*)d_in[6];
    const float* proj_b = (const float*)d_in[7];
    const float* ln2_g  = (const float*)d_in[8];
    const float* ln2_b  = (const float*)d_in[9];
    const float* fc1_w  = (const float*)d_in[10];
    const float* fc1_b  = (const float*)d_in[11];
    const float* fc2_w  = (const float*)d_in[12];
    const float* fc2_b  = (const float*)d_in[13];
    float* outp = (float*)d_out;

    __half *xh, *qkv, *attn, *x2h, *mlp;
    uint4 *w1p, *wpp, *w2p, *w3p;
    float *s1, *cb1, *s2, *cb2, *mu1, *iv1;
    cudaGetSymbolAddress((void**)&xh,   g_xh);
    cudaGetSymbolAddress((void**)&qkv,  g_qkv);
    cudaGetSymbolAddress((void**)&attn, g_attn);
    cudaGetSymbolAddress((void**)&x2h,  g_x2h);
    cudaGetSymbolAddress((void**)&mlp,  g_mlp);
    cudaGetSymbolAddress((void**)&w1p,  g_w1p);
    cudaGetSymbolAddress((void**)&wpp,  g_wpp);
    cudaGetSymbolAddress((void**)&w2p,  g_w2p);
    cudaGetSymbolAddress((void**)&w3p,  g_w3p);
    cudaGetSymbolAddress((void**)&s1,   g_s1);
    cudaGetSymbolAddress((void**)&cb1,  g_cb1);
    cudaGetSymbolAddress((void**)&s2,   g_s2);
    cudaGetSymbolAddress((void**)&cb2,  g_cb2);
    cudaGetSymbolAddress((void**)&mu1,  g_mu1);
    cudaGetSymbolAddress((void**)&iv1,  g_iv1);

    cudaFuncSetAttribute(hgemm<1>, cudaFuncAttributeMaxDynamicSharedMemorySize, SMEM_BYTES);
    cudaFuncSetAttribute(hgemm<3>, cudaFuncAttributeMaxDynamicSharedMemorySize, SMEM_BYTES);
    cudaFuncSetAttribute(hgemm<4>, cudaFuncAttributeMaxDynamicSharedMemorySize, SMEM_BYTES);
    cudaFuncSetAttribute(hgemm<5>, cudaFuncAttributeMaxDynamicSharedMemorySize, SMEM_BYTES);

    // 0) ONE prep launch
    {
        PrepArgs a;
        a.qkv_w = qkv_w; a.proj_w = proj_w; a.fc1_w = fc1_w; a.fc2_w = fc2_w;
        a.ln1_g = ln1_g; a.ln1_b = ln1_b; a.ln2_g = ln2_g; a.ln2_b = ln2_b;
        a.qkv_b = qkv_b; a.fc1_b = fc1_b; a.x = x; a.xh = xh;
        a.w1p = w1p; a.wpp = wpp; a.w2p = w2p; a.w3p = w3p;
        a.s1 = s1; a.cb1 = cb1; a.s2 = s2; a.cb2 = cb2;
        a.mu1 = mu1; a.iv1 = iv1;
        mega_prep<<<PREP_CTAS, 256>>>(a);
    }

    // 1) qkv GEMM with fused LN1 (B = xh) -> qkv fp16
    {
        dim3 grid(HWP / 128, MT_QKV, BB);
        hgemm<4><<<grid, 256, SMEM_BYTES>>>(w1p, xh, cb1, nullptr,
                                            nullptr, qkv, C3, CC, s1, mu1, iv1);
    }

    // 2) attention + softmax (fp16)
    attn_kernel<<<BB * NH * (HWP / ATILE), 256, ATT_SMEM>>>(qkv, relb, attn);

    // 3) proj GEMM + bias + fp16 shortcut(xh) -> x2h
    {
        dim3 grid(HWP / 128, MT_C, BB);
        hgemm<1><<<grid, 256, SMEM_BYTES>>>(wpp, attn, proj_b, xh,
                                            nullptr, x2h, CC, CC, nullptr, nullptr, nullptr);
    }

    // 4) fc1 GEMM with in-CTA LN2 stats + fold + GELU (B = x2h) -> mlp fp16
    {
        dim3 grid(HWP / 128, MT_HID, BB);
        hgemm<5><<<grid, 256, SMEM_BYTES>>>(w2p, x2h, cb2, nullptr,
                                            nullptr, mlp, HID, CC, s2, nullptr, nullptr);
    }

    // 5) fc2 GEMM + bias + fp16 residual(x2h) -> out fp32
    {
        dim3 grid(HWP / 128, MT_C, BB);
        hgemm<3><<<grid, 256, SMEM_BYTES>>>(w3p, mlp, fc2_b, x2h,
                                            outp, nullptr, CC, HID, nullptr, nullptr, nullptr);
    }
}

// round 14
// speedup vs baseline: 1.0924x; 1.0607x over previous
#include <cuda_runtime.h>
#include <cuda_fp16.h>
#include <math.h>
#include <stdint.h>

// Problem dims (fixed by the dataset)
#define BB   16
#define CC   392
#define HWP  4096          // 64*64 pixels
#define NH   8
#define HD   49            // head dim
#define HID  1568          // 4*C
#define C3   1176          // 3*C

#define KT   32
#define KC_C    13
#define KC_HID  49
#define MT_QKV  10
#define MT_C    4
#define MT_HID  13

// ---------------- scratch (static device, no allocs) ----------------
__device__ __half g_xh  [(size_t)BB * CC  * HWP];   // fp16 copy of x
__device__ __half g_qkv [(size_t)BB * C3  * HWP];
__device__ __half g_attn[(size_t)BB * CC  * HWP];
__device__ __half g_x2h [(size_t)BB * CC  * HWP];   // fp16 residual trunk
__device__ __half g_mlp [(size_t)BB * HID * HWP];
// fragment-permuted fp16 weights: [mtile][kchunk][kstep2][mb8][lane32] x uint4
__device__ uint4 g_w1p [(size_t)MT_QKV * KC_C   * 512];
__device__ uint4 g_wpp [(size_t)MT_C   * KC_C   * 512];
__device__ uint4 g_w2p [(size_t)MT_HID * KC_C   * 512];
__device__ uint4 g_w3p [(size_t)MT_C   * KC_HID * 512];
__device__ float g_s1  [C3],  g_cb1[C3];
__device__ float g_s2  [HID], g_cb2[HID];
__device__ float g_mu1 [(size_t)BB * HWP], g_iv1[(size_t)BB * HWP];

// ================= helpers =================
__device__ __forceinline__ uint32_t smem_u32(const void* p) {
    uint32_t a;
    asm("{ .reg .u64 t; cvta.to.shared.u64 t, %1; cvt.u32.u64 %0, t; }"
        : "=r"(a) : "l"(p));
    return a;
}
__device__ __forceinline__ void cp16(uint32_t saddr, const void* g, bool valid) {
    unsigned long long ga;
    asm("cvta.to.global.u64 %0, %1;" : "=l"(ga) : "l"(g));
    int sz = valid ? 16 : 0;
    asm volatile("cp.async.cg.shared.global [%0], [%1], 16, %2;"
                 :: "r"(saddr), "l"(ga), "r"(sz));
}
#define CP_COMMIT() asm volatile("cp.async.commit_group;" ::: "memory")
#define CP_WAIT1()  asm volatile("cp.async.wait_group 1;" ::: "memory")
#define CP_WAIT0()  asm volatile("cp.async.wait_group 0;" ::: "memory")

__device__ __forceinline__ uint32_t pack2(float a, float b) {
    __half2 h = __floats2half2_rn(a, b);
    return *reinterpret_cast<uint32_t*>(&h);
}
__device__ __forceinline__ void mma_f16(float* d, const uint32_t* a, const uint32_t* b) {
    asm volatile(
        "mma.sync.aligned.m16n8k16.row.col.f32.f16.f16.f32 "
        "{%0,%1,%2,%3}, {%4,%5,%6,%7}, {%8,%9}, {%0,%1,%2,%3};"
        : "+f"(d[0]), "+f"(d[1]), "+f"(d[2]), "+f"(d[3])
        : "r"(a[0]), "r"(a[1]), "r"(a[2]), "r"(a[3]), "r"(b[0]), "r"(b[1]));
}
__device__ __forceinline__ void ldmx4t(uint32_t& r0, uint32_t& r1,
                                       uint32_t& r2, uint32_t& r3, uint32_t addr) {
    asm volatile("ldmatrix.sync.aligned.m8n8.x4.trans.shared.b16 {%0,%1,%2,%3}, [%4];"
        : "=r"(r0), "=r"(r1), "=r"(r2), "=r"(r3) : "r"(addr));
}

// ================= fp16 HMMA GEMM (128x64 tile, 4 warps, 4 CTAs/SM) ==========
// D[o, p] = sum_k W[o][k] * X[k][p].  M=128 o, N=64 p, K-chunk 32 (2 k16 steps)
// stage: A 8192 B (fragment order) + B 32 rows x 144 B = 4608 B -> 12800 B
#define STAGES    3
#define B_PITCH   144              // bytes per k-row (64 px * 2B + 16B pad)
#define B_PITCH_H 72               // halves
#define STAGE_B   12800
#define SMEM_BYTES (STAGES * STAGE_B)
#define NTHR      128

// MODE: 1 = +bias + fp16 res(xh), out fp16 (proj -> x2h)
//       3 = +bias + fp16 res(x2h), out fp32 (fc2 -> final)
//       4 = LN-fold via global mu/iv, out fp16 (qkv)
//       5 = LN-fold via in-CTA stats + GELU, out fp16 (fc1)
template<int MODE>
__global__ void __launch_bounds__(NTHR, 4)
hgemm(const uint4* __restrict__ Wp, const __half* __restrict__ X,
      const float* __restrict__ bias, const __half* __restrict__ resh,
      float* __restrict__ out, __half* __restrict__ outh, int O, int K,
      const float* __restrict__ sarr,
      const float* __restrict__ mu, const float* __restrict__ inv)
{
    extern __shared__ float smf[];
    char* smc = reinterpret_cast<char*>(smf);
    const uint32_t sb = smem_u32(smf);
    const int tid  = threadIdx.x;
    const int wid  = tid >> 5;
    const int lane = tid & 31;
    const int r = lane >> 2;
    const int c = lane & 3;
    const int warp_m = (wid >> 1) * 64;    // 0 / 64
    const int warp_n = (wid & 1) * 32;     // 0 / 32
    const int mb0 = warp_m >> 4;

    const int b  = blockIdx.z;
    const int n0 = blockIdx.x * 64;
    const int m0 = blockIdx.y * 128;
    const __half* Xb = X + (size_t)b * K * HWP;
    float*  Ob  = (MODE == 3) ? out + (size_t)b * O * HWP : nullptr;
    __half* Obh = (MODE != 3) ? outh + (size_t)b * O * HWP : nullptr;
    const __half* Rbh = (MODE == 1 || MODE == 3) ? resh + (size_t)b * O * HWP : nullptr;

    const int mvalid = (O - m0 < 128) ? (O - m0) : 128;
    const int rows_w = mvalid - warp_m;

    const int NC = (K + KT - 1) / KT;

    auto load_stage = [&](int stage, int ch) {
        uint32_t a_base = sb + stage * STAGE_B;
        uint32_t b_base = a_base + 8192;
        const uint4* wsrc = Wp + ((size_t)blockIdx.y * NC + ch) * 512;
        #pragma unroll
        for (int i = 0; i < 4; ++i) {               // A: 512 x 16B contiguous
            int slot = tid + i * NTHR;
            cp16(a_base + slot * 16, wsrc + slot, true);
        }
        int k0 = ch * KT;
        #pragma unroll
        for (int i = 0; i < 2; ++i) {               // B: 32 rows x 8 x 16B
            int slot = tid + i * NTHR;
            int kr = slot >> 3, pc = slot & 7;
            int k = k0 + kr;
            bool v = (k < K);
            cp16(b_base + kr * B_PITCH + pc * 16,
                 v ? (const void*)(Xb + (size_t)k * HWP + n0 + pc * 8) : (const void*)Xb, v);
        }
    };

    float acc[4][4][4];
    #pragma unroll
    for (int i = 0; i < 4; ++i)
        #pragma unroll
        for (int j = 0; j < 4; ++j)
            #pragma unroll
            for (int t = 0; t < 4; ++t) acc[i][j][t] = 0.f;

    float psum[4] = {0.f, 0.f, 0.f, 0.f};
    float psq [4] = {0.f, 0.f, 0.f, 0.f};

    load_stage(0, 0);           CP_COMMIT();
    if (NC > 1) load_stage(1, 1);
    CP_COMMIT();

    for (int ch = 0; ch < NC; ++ch) {
        CP_WAIT1();
        __syncthreads();

        int ld = ch + 2;
        if (ld < NC) load_stage(ld % STAGES, ld);
        CP_COMMIT();

        const uint32_t stoff = (uint32_t)((ch % STAGES) * STAGE_B);

        if (rows_w > 0) {
            #pragma unroll
            for (int ks = 0; ks < 2; ++ks) {
                uint32_t af[4][4];
                #pragma unroll
                for (int mt = 0; mt < 4; ++mt) {
                    if (mt * 16 >= rows_w) continue;
                    uint4 v = *reinterpret_cast<const uint4*>(
                        smc + stoff + (ks * 256 + (mb0 + mt) * 32 + lane) * 16);
                    af[mt][0] = v.x; af[mt][1] = v.y;
                    af[mt][2] = v.z; af[mt][3] = v.w;
                }
                uint32_t bf[8];
                int rl = ks * 16 + (lane & 15);
                uint32_t baddr = sb + stoff + 8192 + rl * B_PITCH
                               + (warp_n + ((lane >> 4) << 3)) * 2;
                ldmx4t(bf[0], bf[1], bf[2], bf[3], baddr);
                ldmx4t(bf[4], bf[5], bf[6], bf[7], baddr + 32);
                #pragma unroll
                for (int mt = 0; mt < 4; ++mt) {
                    if (mt * 16 >= rows_w) continue;
                    #pragma unroll
                    for (int nt = 0; nt < 4; ++nt)
                        mma_f16(acc[mt][nt], af[mt], bf + nt * 2);
                }
            }
        }

        if (MODE == 5) {
            // per-pixel sum/sumsq of this stage's B tile (64 px).
            // thread owns px quad (tid&15)*4, rows (tid>>4)+8i.
            const __half* Bsh = reinterpret_cast<const __half*>(smc + stoff + 8192);
            #pragma unroll
            for (int i = 0; i < 4; ++i) {
                int kr = (tid >> 4) + 8 * i;
                const __half2* hp = reinterpret_cast<const __half2*>(
                    Bsh + kr * B_PITCH_H + (tid & 15) * 4);
                float2 f0 = __half22float2(hp[0]);
                float2 f1 = __half22float2(hp[1]);
                psum[0] += f0.x; psq[0] = fmaf(f0.x, f0.x, psq[0]);
                psum[1] += f0.y; psq[1] = fmaf(f0.y, f0.y, psq[1]);
                psum[2] += f1.x; psq[2] = fmaf(f1.x, f1.x, psq[2]);
                psum[3] += f1.y; psq[3] = fmaf(f1.y, f1.y, psq[3]);
            }
        }
    }

    if (MODE == 5) {
        // cross-group reduction through reused stage smem
        CP_WAIT0();
        __syncthreads();
        int g8 = tid >> 4, q4 = (tid & 15) * 4;
        #pragma unroll
        for (int j = 0; j < 4; ++j) {
            smf[g8 * 64 + q4 + j]       = psum[j];
            smf[512 + g8 * 64 + q4 + j] = psq[j];
        }
        __syncthreads();
        if (tid < 64) {
            float s = 0.f, q = 0.f;
            #pragma unroll
            for (int w = 0; w < 8; ++w) {
                s += smf[w * 64 + tid];
                q += smf[512 + w * 64 + tid];
            }
            float m  = s * (1.0f / CC);
            float iv = rsqrtf(q * (1.0f / CC) - m * m + 1e-5f);
            smf[1024 + tid] = m;
            smf[1088 + tid] = iv;
        }
        __syncthreads();
    }

    // ---- epilogue ----
    float2 m2[4], i2[4];
    if (MODE == 4) {
        const float* muB = mu  + (size_t)b * HWP + n0;
        const float* ivB = inv + (size_t)b * HWP + n0;
        #pragma unroll
        for (int nt = 0; nt < 4; ++nt) {
            int p = warp_n + nt * 8 + c * 2;
            m2[nt] = *reinterpret_cast<const float2*>(muB + p);
            i2[nt] = *reinterpret_cast<const float2*>(ivB + p);
        }
    }
    if (MODE == 5) {
        #pragma unroll
        for (int nt = 0; nt < 4; ++nt) {
            int p = warp_n + nt * 8 + c * 2;
            m2[nt] = *reinterpret_cast<const float2*>(smf + 1024 + p);
            i2[nt] = *reinterpret_cast<const float2*>(smf + 1088 + p);
        }
    }
    #pragma unroll
    for (int mt = 0; mt < 4; ++mt) {
        #pragma unroll
        for (int half = 0; half < 2; ++half) {
            int o = m0 + warp_m + mt * 16 + half * 8 + r;
            if (o >= O) continue;
            float bv = bias[o];
            float so = (MODE >= 4) ? sarr[o] : 0.f;
            #pragma unroll
            for (int nt = 0; nt < 4; ++nt) {
                int p = n0 + warp_n + nt * 8 + c * 2;
                float v0 = acc[mt][nt][half * 2 + 0];
                float v1 = acc[mt][nt][half * 2 + 1];
                if (MODE == 1 || MODE == 3) {
                    float2 rv = __half22float2(
                        *reinterpret_cast<const __half2*>(Rbh + (size_t)o * HWP + p));
                    v0 += bv + rv.x; v1 += bv + rv.y;
                } else {
                    v0 = i2[nt].x * (v0 - m2[nt].x * so) + bv;
                    v1 = i2[nt].y * (v1 - m2[nt].y * so) + bv;
                    if (MODE == 5) {
                        v0 = 0.5f * v0 * (1.0f + erff(v0 * 0.70710678118654752f));
                        v1 = 0.5f * v1 * (1.0f + erff(v1 * 0.70710678118654752f));
                    }
                }
                if (MODE == 3)
                    *reinterpret_cast<float2*>(Ob + (size_t)o * HWP + p)
                        = make_float2(v0, v1);
                else
                    *reinterpret_cast<__half2*>(Obh + (size_t)o * HWP + p)
                        = __floats2half2_rn(v0, v1);
            }
        }
    }
}

// ================= mega-prep (one launch) ====================================
#define XH_CTAS  (BB * CC * HWP / (256 * 8))     // 12544
#define P1_CTAS  (MT_QKV * KC_C * 2)             // 260
#define P2_CTAS  (MT_C   * KC_C * 2)             // 104
#define P3_CTAS  (MT_HID * KC_C * 2)             // 338
#define P4_CTAS  (MT_C   * KC_HID * 2)           // 392
#define SCB1_CTAS ((C3  * 32 + 255) / 256)
#define SCB2_CTAS ((HID * 32 + 255) / 256)
#define STAT_CTAS (BB * HWP / 256)
#define PREP_CTAS (XH_CTAS + P1_CTAS + P2_CTAS + P3_CTAS + P4_CTAS + \
                   SCB1_CTAS + SCB2_CTAS + STAT_CTAS)

struct PrepArgs {
    const float *qkv_w, *proj_w, *fc1_w, *fc2_w;
    const float *ln1_g, *ln1_b, *ln2_g, *ln2_b;
    const float *qkv_b, *fc1_b;
    const float *x;
    __half *xh;
    uint4 *w1p, *wpp, *w2p, *w3p;
    float *s1, *cb1, *s2, *cb2;
    float *mu1, *iv1;
};

__device__ __forceinline__ void do_perm_h(
    const float* __restrict__ W, const float* __restrict__ g,
    uint4* __restrict__ Wp, int O, int K, int Kc, size_t gid)
{
    int lane = (int)(gid & 31);
    int mb   = (int)((gid >> 5) & 7);
    int ks   = (int)((gid >> 8) & 1);
    size_t t = gid >> 9;
    int ch = (int)(t % Kc);
    int mt = (int)(t / Kc);
    int r = lane >> 2, c = lane & 3;
    int row0 = mt * 128 + mb * 16 + r, row1 = row0 + 8;
    int k0 = ch * 32 + ks * 16 + 2 * c;
    float w00=0.f,w01=0.f,w02=0.f,w03=0.f,w10=0.f,w11=0.f,w12=0.f,w13=0.f;
    auto ld = [&](int rr, int kk) -> float {
        return (kk < K) ? W[(size_t)rr * K + kk] * (g ? g[kk] : 1.f) : 0.f;
    };
    if (row0 < O) { w00=ld(row0,k0); w01=ld(row0,k0+1); w02=ld(row0,k0+8); w03=ld(row0,k0+9); }
    if (row1 < O) { w10=ld(row1,k0); w11=ld(row1,k0+1); w12=ld(row1,k0+8); w13=ld(row1,k0+9); }
    uint4 o;
    o.x = pack2(w00, w01); o.y = pack2(w10, w11);
    o.z = pack2(w02, w03); o.w = pack2(w12, w13);
    Wp[gid] = o;
}

__device__ __forceinline__ void do_scb(
    const float* __restrict__ W, const float* __restrict__ g,
    const float* __restrict__ bta, const float* __restrict__ bias,
    float* __restrict__ sarr, float* __restrict__ cb, int O, int K,
    int idx, int lane)
{
    int w = idx >> 5;
    if (w >= O) return;
    float ss = 0.f, bs = 0.f;
    for (int k = lane; k < K; k += 32) {
        float wv = W[(size_t)w * K + k];
        ss += wv * g[k];
        bs += wv * bta[k];
    }
    #pragma unroll
    for (int off = 16; off; off >>= 1) {
        ss += __shfl_xor_sync(0xFFFFFFFFu, ss, off);
        bs += __shfl_xor_sync(0xFFFFFFFFu, bs, off);
    }
    if (lane == 0) { sarr[w] = ss; cb[w] = bias[w] + bs; }
}

__global__ void __launch_bounds__(256) mega_prep(PrepArgs a)
{
    int cta = blockIdx.x;
    int tid = threadIdx.x;
    if (cta < XH_CTAS) {   // x -> fp16
        size_t i0 = ((size_t)cta * 256 + tid) * 8;
        float4 f0 = *reinterpret_cast<const float4*>(a.x + i0);
        float4 f1 = *reinterpret_cast<const float4*>(a.x + i0 + 4);
        uint4 o;
        o.x = pack2(f0.x, f0.y); o.y = pack2(f0.z, f0.w);
        o.z = pack2(f1.x, f1.y); o.w = pack2(f1.z, f1.w);
        *reinterpret_cast<uint4*>(a.xh + i0) = o;
        return;
    }
    cta -= XH_CTAS;
    if (cta < P1_CTAS) { do_perm_h(a.qkv_w, a.ln1_g, a.w1p, C3, CC, KC_C, (size_t)cta*256+tid); return; }
    cta -= P1_CTAS;
    if (cta < P2_CTAS) { do_perm_h(a.proj_w, nullptr, a.wpp, CC, CC, KC_C, (size_t)cta*256+tid); return; }
    cta -= P2_CTAS;
    if (cta < P3_CTAS) { do_perm_h(a.fc1_w, a.ln2_g, a.w2p, HID, CC, KC_C, (size_t)cta*256+tid); return; }
    cta -= P3_CTAS;
    if (cta < P4_CTAS) { do_perm_h(a.fc2_w, nullptr, a.w3p, CC, HID, KC_HID, (size_t)cta*256+tid); return; }
    cta -= P4_CTAS;
    if (cta < SCB1_CTAS) { do_scb(a.qkv_w, a.ln1_g, a.ln1_b, a.qkv_b, a.s1, a.cb1, C3, CC, cta*256+tid, tid&31); return; }
    cta -= SCB1_CTAS;
    if (cta < SCB2_CTAS) { do_scb(a.fc1_w, a.ln2_g, a.ln2_b, a.fc1_b, a.s2, a.cb2, HID, CC, cta*256+tid, tid&31); return; }
    cta -= SCB2_CTAS;
    {   // LN1 stats (fp32 x)
        int idx = cta * 256 + tid;
        int b = idx / HWP;
        int p = idx - b * HWP;
        const float* xb = a.x + (size_t)b * CC * HWP + p;
        float s = 0.f, s2 = 0.f;
        #pragma unroll 8
        for (int c = 0; c < CC; c++) {
            float v = xb[(size_t)c * HWP];
            s += v; s2 += v * v;
        }
        float m  = s * (1.0f / CC);
        float var = s2 * (1.0f / CC) - m * m;
        a.mu1[idx] = m;
        a.iv1[idx] = rsqrtf(var + 1e-5f);
    }
}

// ---------------- attention + softmax (fp16 in/out, smem-staged writes) ------
#define ATILE 256
#define ATT_SMEM (ATILE * HD * 2)     // 25088 bytes

__global__ void __launch_bounds__(256) attn_kernel(
    const __half* __restrict__ qkv, const float* __restrict__ rel_bias,
    __half* __restrict__ out)
{
    extern __shared__ __half smh[];
    const int tid = threadIdx.x;
    int tile = blockIdx.x;
    int p0   = (tile & 15) * ATILE;
    int bh   = tile >> 4;
    int head = bh & (NH - 1);
    int b    = bh >> 3;
    int p    = p0 + tid;

    const __half* base = qkv + (size_t)b * C3 * HWP;
    const __half* qp = base + (size_t)(head * HD) * HWP + p;
    const __half* kp = base + (size_t)(CC + head * HD) * HWP + p;
    const __half* vp = base + (size_t)(2 * CC + head * HD) * HWP + p;
    const float scale = 0.14285714285714285f;   // 49^-0.5

    float s[HD];
    float mx = -INFINITY;
    #pragma unroll
    for (int d = 0; d < HD; d++) {
        float sv = __half2float(qp[(size_t)d * HWP]) * scale
                 * __half2float(kp[(size_t)d * HWP]) + rel_bias[head * HD + d];
        s[d] = sv;
        mx = fmaxf(mx, sv);
    }
    float sum = 0.f;
    #pragma unroll
    for (int d = 0; d < HD; d++) {
        float e = __expf(s[d] - mx);
        s[d] = e;
        sum += e;
    }
    float inv = 1.0f / sum;
    __half* st = smh + tid * HD;
    #pragma unroll
    for (int d = 0; d < HD; d++) {
        st[d] = __float2half_rn(s[d] * inv * __half2float(vp[(size_t)d * HWP]));
    }
    __syncthreads();

    uint4* dst = reinterpret_cast<uint4*>(
        out + (size_t)b * CC * HWP + (size_t)head * HWP * HD + (size_t)p0 * HD);
    const uint4* src = reinterpret_cast<const uint4*>(smh);
    #pragma unroll
    for (int i = tid; i < ATILE * HD / 8; i += 256)
        dst[i] = src[i];
}

// ---------------- launch ----------------
extern "C" void kernel_launch(void* const* d_in, const int* in_sizes, int n_in,
                              void* d_out, int out_size)
{
    const float* x      = (const float*)d_in[0];
    const float* ln1_g  = (const float*)d_in[1];
    const float* ln1_b  = (const float*)d_in[2];
    const float* qkv_w  = (const float*)d_in[3];
    const float* qkv_b  = (const float*)d_in[4];
    const float* relb   = (const float*)d_in[5];
    const float* proj_w = (const float*)d_in[6];
    const float* proj_b = (const float*)d_in[7];
    const float* ln2_g  = (const float*)d_in[8];
    const float* ln2_b  = (const float*)d_in[9];
    const float* fc1_w  = (const float*)d_in[10];
    const float* fc1_b  = (const float*)d_in[11];
    const float* fc2_w  = (const float*)d_in[12];
    const float* fc2_b  = (const float*)d_in[13];
    float* outp = (float*)d_out;

    __half *xh, *qkv, *attn, *x2h, *mlp;
    uint4 *w1p, *wpp, *w2p, *w3p;
    float *s1, *cb1, *s2, *cb2, *mu1, *iv1;
    cudaGetSymbolAddress((void**)&xh,   g_xh);
    cudaGetSymbolAddress((void**)&qkv,  g_qkv);
    cudaGetSymbolAddress((void**)&attn, g_attn);
    cudaGetSymbolAddress((void**)&x2h,  g_x2h);
    cudaGetSymbolAddress((void**)&mlp,  g_mlp);
    cudaGetSymbolAddress((void**)&w1p,  g_w1p);
    cudaGetSymbolAddress((void**)&wpp,  g_wpp);
    cudaGetSymbolAddress((void**)&w2p,  g_w2p);
    cudaGetSymbolAddress((void**)&w3p,  g_w3p);
    cudaGetSymbolAddress((void**)&s1,   g_s1);
    cudaGetSymbolAddress((void**)&cb1,  g_cb1);
    cudaGetSymbolAddress((void**)&s2,   g_s2);
    cudaGetSymbolAddress((void**)&cb2,  g_cb2);
    cudaGetSymbolAddress((void**)&mu1,  g_mu1);
    cudaGetSymbolAddress((void**)&iv1,  g_iv1);

    cudaFuncSetAttribute(hgemm<1>, cudaFuncAttributeMaxDynamicSharedMemorySize, SMEM_BYTES);
    cudaFuncSetAttribute(hgemm<3>, cudaFuncAttributeMaxDynamicSharedMemorySize, SMEM_BYTES);
    cudaFuncSetAttribute(hgemm<4>, cudaFuncAttributeMaxDynamicSharedMemorySize, SMEM_BYTES);
    cudaFuncSetAttribute(hgemm<5>, cudaFuncAttributeMaxDynamicSharedMemorySize, SMEM_BYTES);

    // 0) ONE prep launch
    {
        PrepArgs a;
        a.qkv_w = qkv_w; a.proj_w = proj_w; a.fc1_w = fc1_w; a.fc2_w = fc2_w;
        a.ln1_g = ln1_g; a.ln1_b = ln1_b; a.ln2_g = ln2_g; a.ln2_b = ln2_b;
        a.qkv_b = qkv_b; a.fc1_b = fc1_b; a.x = x; a.xh = xh;
        a.w1p = w1p; a.wpp = wpp; a.w2p = w2p; a.w3p = w3p;
        a.s1 = s1; a.cb1 = cb1; a.s2 = s2; a.cb2 = cb2;
        a.mu1 = mu1; a.iv1 = iv1;
        mega_prep<<<PREP_CTAS, 256>>>(a);
    }

    // 1) qkv GEMM with fused LN1 (B = xh) -> qkv fp16
    {
        dim3 grid(HWP / 64, MT_QKV, BB);
        hgemm<4><<<grid, NTHR, SMEM_BYTES>>>(w1p, xh, cb1, nullptr,
                                             nullptr, qkv, C3, CC, s1, mu1, iv1);
    }

    // 2) attention + softmax (fp16)
    attn_kernel<<<BB * NH * (HWP / ATILE), 256, ATT_SMEM>>>(qkv, relb, attn);

    // 3) proj GEMM + bias + fp16 shortcut(xh) -> x2h
    {
        dim3 grid(HWP / 64, MT_C, BB);
        hgemm<1><<<grid, NTHR, SMEM_BYTES>>>(wpp, attn, proj_b, xh,
                                             nullptr, x2h, CC, CC, nullptr, nullptr, nullptr);
    }

    // 4) fc1 GEMM with in-CTA LN2 stats + fold + GELU (B = x2h) -> mlp fp16
    {
        dim3 grid(HWP / 64, MT_HID, BB);
        hgemm<5><<<grid, NTHR, SMEM_BYTES>>>(w2p, x2h, cb2, nullptr,
                                             nullptr, mlp, HID, CC, s2, nullptr, nullptr);
    }

    // 5) fc2 GEMM + bias + fp16 residual(x2h) -> out fp32
    {
        dim3 grid(HWP / 64, MT_C, BB);
        hgemm<3><<<grid, NTHR, SMEM_BYTES>>>(w3p, mlp, fc2_b, x2h,
                                             outp, nullptr, CC, HID, nullptr, nullptr, nullptr);
    }
}